// round 6
// baseline (speedup 1.0000x reference)
#include <cuda_runtime.h>
#include <cuda_fp16.h>
#include <cstdint>

#define NV 778
#define NK 9
#define NC 256
#define NB 64
#define B3 192
#define MROWS (NB * NV)   // 49792

// ---------------- scratch (device globals; no runtime allocation) ----------------
__device__ __half g_h0h[(size_t)MROWS * 512];
__device__ __half g_h1h[(size_t)MROWS * 512];
__device__ __half g_h2h[(size_t)MROWS * 256];
__device__ float  g_h3 [(size_t)MROWS * 256];
__device__ __half g_wt0[512 * 4608];   // [N][K]
__device__ __half g_wt1[256 * 4608];
__device__ __half g_wt2[256 * 2304];
__device__ float  g_occ[B3 * 5];
__device__ int    g_assign[NV];

// ---------------- stage 0: occ + per-vertex finger assignment ----------------
__global__ void prep_kernel(const float* __restrict__ pred,
                            const int* __restrict__ f0, int n0,
                            const int* __restrict__ f1, int n1,
                            const int* __restrict__ f2, int n2,
                            const int* __restrict__ f3, int n3,
                            const int* __restrict__ f4, int n4) {
    int t = threadIdx.x;
    for (int i = t; i < B3 * 5; i += 256) {
        int b = i / 5, f = i % 5;
        float p0 = pred[b * 10 + f];
        float p1 = pred[b * 10 + 5 + f];
        g_occ[i] = 1.f / (1.f + __expf(p1 - p0));
    }
    for (int i = t; i < NV; i += 256) g_assign[i] = -1;
    __syncthreads();
    if (t < n0) g_assign[f0[t]] = 0;
    __syncthreads();
    if (t < n1) g_assign[f1[t]] = 1;
    __syncthreads();
    if (t < n2) g_assign[f2[t]] = 2;
    __syncthreads();
    if (t < n3) g_assign[f3[t]] = 3;
    __syncthreads();
    if (t < n4) g_assign[f4[t]] = 4;
}

// ---------------- weight transpose + fp16 convert: dst[n][k] = (half)src[k][n] ----------------
__global__ void transconv_kernel(const float* __restrict__ src, __half* __restrict__ dst,
                                 int K, int N) {
    __shared__ float tile[32][33];
    int n0 = blockIdx.x * 32, k0 = blockIdx.y * 32;
    int x = threadIdx.x;
    for (int yy = threadIdx.y; yy < 32; yy += 8) {
        int k = k0 + yy, n = n0 + x;
        tile[yy][x] = (k < K && n < N) ? src[(size_t)k * N + n] : 0.f;
    }
    __syncthreads();
    for (int yy = threadIdx.y; yy < 32; yy += 8) {
        int n = n0 + yy, k = k0 + x;
        if (n < N && k < K) dst[(size_t)n * K + k] = __float2half_rn(tile[x][yy]);
    }
}

// ---------------- stage 1: weighted view fusion -> h0 = [wx | x[:B]] (fp16) ----------------
__global__ void h0_kernel(const float* __restrict__ x) {
    int v = blockIdx.x;
    int b = blockIdx.y;
    int c = threadIdx.x;
    int a = g_assign[v];
    float w0 = 1.f, w1 = 1.f, w2 = 1.f;
    if (a >= 0) {
        w0 = g_occ[(0 * NB + b) * 5 + a];
        w1 = g_occ[(1 * NB + b) * 5 + a];
        w2 = g_occ[(2 * NB + b) * 5 + a];
    }
    float m  = fmaxf(w0, fmaxf(w1, w2));
    float e0 = __expf(w0 - m), e1 = __expf(w1 - m), e2 = __expf(w2 - m);
    float inv = 1.f / (e0 + e1 + e2);
    size_t base = ((size_t)b * NV + v) * NC + c;
    const size_t gstride = (size_t)NB * NV * NC;
    float x0 = x[base];
    float x1 = x[base + gstride];
    float x2 = x[base + 2 * gstride];
    size_t ho = ((size_t)b * NV + v) * 512 + c;
    g_h0h[ho]       = __float2half_rn((e0 * x0 + e1 * x1 + e2 * x2) * inv);
    g_h0h[ho + 256] = __float2half_rn(x0);
}

// ---------------- fp16 mma.sync implicit-gather GEMM ----------------
// CTA 256x128, K-chunk 64 fp16, 3-stage cp.async pipeline (wait_group 1),
// ldmatrix fragments. 8 warps: 4M x 2N, warp tile 64x64.
#define OF_NBR   0
#define OF_TILES 9216
#define STG_A    32768u
#define STG_B    16384u
#define STG_SZ   49152u
#define SMEM_H   (OF_TILES + 3 * 49152)   // 156672 B

__device__ __forceinline__ uint32_t smem_u32(const void* p) {
    uint32_t a;
    asm("{ .reg .u64 t; cvta.to.shared.u64 t, %1; cvt.u32.u64 %0, t; }" : "=r"(a) : "l"(p));
    return a;
}
#define CPASYNC16(dst, src) \
    asm volatile("cp.async.cg.shared.global [%0], [%1], 16;" :: "r"(dst), "l"(src))
#define CPCOMMIT()  asm volatile("cp.async.commit_group;" ::: "memory")
#define CPWAIT(n)   asm volatile("cp.async.wait_group %0;" :: "n"(n) : "memory")
#define LDSM4(r0, r1, r2, r3, addr) \
    asm volatile("ldmatrix.sync.aligned.m8n8.x4.shared.b16 {%0,%1,%2,%3}, [%4];" \
                 : "=r"(r0), "=r"(r1), "=r"(r2), "=r"(r3) : "r"(addr))
#define MMA16816(d, a, b) \
    asm volatile("mma.sync.aligned.m16n8k16.row.col.f32.f16.f16.f32 " \
                 "{%0,%1,%2,%3}, {%4,%5,%6,%7}, {%8,%9}, {%0,%1,%2,%3};" \
                 : "+f"(d[0]), "+f"(d[1]), "+f"(d[2]), "+f"(d[3]) \
                 : "r"(a[0]), "r"(a[1]), "r"(a[2]), "r"(a[3]), "r"(b[0]), "r"(b[1]))

template<int CIN, int KTOT, int COUT, int LOGCPW, bool OUTF32>
__global__ __launch_bounds__(256)
void spiral_hmma(const __half* __restrict__ hin,
                 const __half* __restrict__ wt,    // [COUT][KTOT] fp16
                 const float* __restrict__ bias,
                 const int* __restrict__ idx,
                 void* __restrict__ houtv) {
    extern __shared__ char sm[];
    int* nb_s = (int*)(sm + OF_NBR);
    const uint32_t smT = smem_u32(sm + OF_TILES);
    const int tid  = threadIdx.x;
    const int lane = tid & 31;
    const int wid  = tid >> 5;
    const int warpM = wid & 3;
    const int warpN = wid >> 2;
    const int n0 = blockIdx.x * 128;
    const int m0 = blockIdx.y * 256;

    {
        int grow = m0 + tid;
        bool ok = grow < MROWS;
        int b = ok ? grow / NV : 0;
        int v = ok ? grow - b * NV : 0;
#pragma unroll
        for (int k = 0; k < NK; k++) nb_s[tid * NK + k] = b * NV + idx[v * NK + k];
    }
    __syncthreads();

    constexpr int CPW = CIN / 64;
    constexpr int NCH = KTOT / 64;

    // cp.async geometry
    const int asw   = tid & 7;                       // A: one row per thread
    const uint32_t adst0 = smT + (uint32_t)tid * 128u;
    const int blrow = tid >> 1;                      // B: half-row per thread
    const int bjh   = (tid & 1) * 4;
    const int blsw  = blrow & 7;
    const uint32_t bdst0 = smT + STG_A + (uint32_t)blrow * 128u;
    const __half* brow_src = wt + (size_t)(n0 + blrow) * KTOT;

#define LOAD_CHUNK(kc, stg)                                                        \
    {                                                                              \
        const int ks = (kc) >> LOGCPW;                                             \
        const int c0 = ((kc) & (CPW - 1)) * 64;                                    \
        const __half* asrc = hin + (size_t)nb_s[tid * NK + ks] * CIN + c0;         \
        const uint32_t ad = adst0 + (uint32_t)(stg) * STG_SZ;                      \
        const uint32_t bd = bdst0 + (uint32_t)(stg) * STG_SZ;                      \
        const __half* bsrc = brow_src + (size_t)(kc) * 64;                         \
        _Pragma("unroll")                                                          \
        for (int c = 0; c < 8; c++)                                                \
            CPASYNC16(ad + (uint32_t)((c ^ asw) << 4), asrc + c * 8);              \
        _Pragma("unroll")                                                          \
        for (int jj = 0; jj < 4; jj++) {                                           \
            const int c = bjh + jj;                                                \
            CPASYNC16(bd + (uint32_t)((c ^ blsw) << 4), bsrc + c * 8);             \
        }                                                                          \
        CPCOMMIT();                                                                \
    }

    // ldmatrix geometry
    const int arow0 = warpM * 64 + (lane & 15);
    const int ahi   = (lane >> 4) & 1;
    const int brow0 = warpN * 64 + (lane & 7) + ((lane & 16) >> 1);
    const int bhi   = (lane >> 3) & 1;

    float acc[4][8][4];
#pragma unroll
    for (int a = 0; a < 4; a++)
#pragma unroll
        for (int b = 0; b < 8; b++)
#pragma unroll
            for (int c = 0; c < 4; c++) acc[a][b][c] = 0.f;

    LOAD_CHUNK(0, 0);
    LOAD_CHUNK(1, 1);
    int stg = 0;
    for (int kc = 0; kc < NCH; kc++) {
        CPWAIT(1);
        __syncthreads();
        if (kc + 2 < NCH) {
            int ns = stg + 2; if (ns >= 3) ns -= 3;
            LOAD_CHUNK(kc + 2, ns);
        }
        const uint32_t aBuf = smT + (uint32_t)stg * STG_SZ;
        const uint32_t bBuf = aBuf + STG_A;
#pragma unroll
        for (int s = 0; s < 4; s++) {
            uint32_t afr[4][4];
#pragma unroll
            for (int mt = 0; mt < 4; mt++) {
                const int ar = arow0 + mt * 16;
                LDSM4(afr[mt][0], afr[mt][1], afr[mt][2], afr[mt][3],
                      aBuf + (uint32_t)ar * 128u + (uint32_t)((((s * 2 + ahi) ^ (ar & 7))) << 4));
            }
            uint32_t bfr[8][2];
#pragma unroll
            for (int p = 0; p < 4; p++) {
                const int br = brow0 + p * 16;
                LDSM4(bfr[p * 2][0], bfr[p * 2][1], bfr[p * 2 + 1][0], bfr[p * 2 + 1][1],
                      bBuf + (uint32_t)br * 128u + (uint32_t)((((s * 2 + bhi) ^ (br & 7))) << 4));
            }
#pragma unroll
            for (int mt = 0; mt < 4; mt++)
#pragma unroll
                for (int nt = 0; nt < 8; nt++)
                    MMA16816(acc[mt][nt], afr[mt], bfr[nt]);
        }
        __syncthreads();
        stg++; if (stg == 3) stg = 0;
    }

    // epilogue: bias + relu; fp16 out for next conv, fp32 for head input
    const int r4 = lane >> 2;
    const int c2 = (lane & 3) * 2;
#pragma unroll
    for (int nt = 0; nt < 8; nt++) {
        const int col = n0 + warpN * 64 + nt * 8 + c2;
        const float b0v = bias[col], b1v = bias[col + 1];
#pragma unroll
        for (int mt = 0; mt < 4; mt++) {
            const int row = m0 + warpM * 64 + mt * 16 + r4;
            if (row + 8 < MROWS) {   // full 16-row group valid (MROWS % 128 == 0)
                float v0 = fmaxf(acc[mt][nt][0] + b0v, 0.f);
                float v1 = fmaxf(acc[mt][nt][1] + b1v, 0.f);
                float v2 = fmaxf(acc[mt][nt][2] + b0v, 0.f);
                float v3 = fmaxf(acc[mt][nt][3] + b1v, 0.f);
                if (OUTF32) {
                    float* ho = (float*)houtv;
                    *(float2*)(ho + (size_t)row * COUT + col) = make_float2(v0, v1);
                    *(float2*)(ho + (size_t)(row + 8) * COUT + col) = make_float2(v2, v3);
                } else {
                    __half2* ho = (__half2*)houtv;
                    ho[((size_t)row * COUT + col) >> 1] = __floats2half2_rn(v0, v1);
                    ho[((size_t)(row + 8) * COUT + col) >> 1] = __floats2half2_rn(v2, v3);
                }
            }
        }
    }
#undef LOAD_CHUNK
}

// ---------------- head: Cout=3, one warp per (b,v) row ----------------
__global__ __launch_bounds__(256)
void head_kernel(const float* __restrict__ h3,
                 const float* __restrict__ wh,
                 const float* __restrict__ bh,
                 const int* __restrict__ idx,
                 float* __restrict__ out) {
    int warp = blockIdx.x * 8 + (threadIdx.x >> 5);
    int lane = threadIdx.x & 31;
    int b = warp / NV;
    int v = warp - b * NV;
    const float* hb = h3 + (size_t)b * NV * NC;
    float a0 = 0.f, a1 = 0.f, a2 = 0.f;
    for (int t = lane; t < NK * NC; t += 32) {
        int k = t >> 8;
        int c = t & 255;
        float a = hb[(size_t)idx[v * NK + k] * NC + c];
        const float* wr = wh + t * 3;
        a0 += a * wr[0];
        a1 += a * wr[1];
        a2 += a * wr[2];
    }
#pragma unroll
    for (int off = 16; off; off >>= 1) {
        a0 += __shfl_down_sync(0xffffffffu, a0, off);
        a1 += __shfl_down_sync(0xffffffffu, a1, off);
        a2 += __shfl_down_sync(0xffffffffu, a2, off);
    }
    if (lane == 0) {
        float* o = out + (size_t)warp * 3;
        o[0] = a0 + bh[0];
        o[1] = a1 + bh[1];
        o[2] = a2 + bh[2];
    }
}

// ---------------- launch ----------------
extern "C" void kernel_launch(void* const* d_in, const int* in_sizes, int n_in,
                              void* d_out, int out_size) {
    const float* x        = (const float*)d_in[0];
    const float* pred_occ = (const float*)d_in[1];
    const int*   indices  = (const int*)d_in[2];
    const int*   f0 = (const int*)d_in[3];
    const int*   f1 = (const int*)d_in[4];
    const int*   f2 = (const int*)d_in[5];
    const int*   f3 = (const int*)d_in[6];
    const int*   f4 = (const int*)d_in[7];
    const float* w0 = (const float*)d_in[8];
    const float* b0 = (const float*)d_in[9];
    const float* w1 = (const float*)d_in[10];
    const float* b1 = (const float*)d_in[11];
    const float* w2 = (const float*)d_in[12];
    const float* b2 = (const float*)d_in[13];
    const float* wh = (const float*)d_in[14];
    const float* bh = (const float*)d_in[15];
    float* out = (float*)d_out;

    __half *h0p, *h1p, *h2p, *wt0p, *wt1p, *wt2p;
    float *h3p;
    cudaGetSymbolAddress((void**)&h0p, g_h0h);
    cudaGetSymbolAddress((void**)&h1p, g_h1h);
    cudaGetSymbolAddress((void**)&h2p, g_h2h);
    cudaGetSymbolAddress((void**)&h3p, g_h3);
    cudaGetSymbolAddress((void**)&wt0p, g_wt0);
    cudaGetSymbolAddress((void**)&wt1p, g_wt1);
    cudaGetSymbolAddress((void**)&wt2p, g_wt2);

    cudaFuncSetAttribute(spiral_hmma<512, 4608, 512, 3, false>, cudaFuncAttributeMaxDynamicSharedMemorySize, SMEM_H);
    cudaFuncSetAttribute(spiral_hmma<512, 4608, 256, 3, false>, cudaFuncAttributeMaxDynamicSharedMemorySize, SMEM_H);
    cudaFuncSetAttribute(spiral_hmma<256, 2304, 256, 2, true>, cudaFuncAttributeMaxDynamicSharedMemorySize, SMEM_H);

    prep_kernel<<<1, 256>>>(pred_occ, f0, in_sizes[3], f1, in_sizes[4],
                            f2, in_sizes[5], f3, in_sizes[6], f4, in_sizes[7]);
    transconv_kernel<<<dim3(512 / 32, 4608 / 32), dim3(32, 8)>>>(w0, wt0p, 4608, 512);
    transconv_kernel<<<dim3(256 / 32, 4608 / 32), dim3(32, 8)>>>(w1, wt1p, 4608, 256);
    transconv_kernel<<<dim3(256 / 32, 2304 / 32), dim3(32, 8)>>>(w2, wt2p, 2304, 256);
    h0_kernel<<<dim3(NV, NB), 256>>>(x);

    spiral_hmma<512, 4608, 512, 3, false><<<dim3(4, 195), 256, SMEM_H>>>(h0p, wt0p, b0, indices, h1p);
    spiral_hmma<512, 4608, 256, 3, false><<<dim3(2, 195), 256, SMEM_H>>>(h1p, wt1p, b1, indices, h2p);
    spiral_hmma<256, 2304, 256, 2, true><<<dim3(2, 195), 256, SMEM_H>>>(h2p, wt2p, b2, indices, h3p);
    head_kernel<<<6224, 256>>>(h3p, wh, bh, indices, out);
}

// round 7
// speedup vs baseline: 1.2810x; 1.2810x over previous
#include <cuda_runtime.h>
#include <cuda_fp16.h>
#include <cstdint>

#define NV 778
#define NK 9
#define NC 256
#define NB 64
#define B3 192
#define MROWS (NB * NV)   // 49792 = 389 * 128 exactly

// ---------------- scratch (device globals; no runtime allocation) ----------------
__device__ __half g_h0h[(size_t)MROWS * 512];
__device__ __half g_h1h[(size_t)MROWS * 512];
__device__ __half g_h2h[(size_t)MROWS * 256];
__device__ float  g_h3 [(size_t)MROWS * 256];
__device__ __half g_wt0[512 * 4608];   // [N][K]
__device__ __half g_wt1[256 * 4608];
__device__ __half g_wt2[256 * 2304];
__device__ float  g_occ[B3 * 5];
__device__ int    g_assign[NV];

// ---------------- stage 0: occ + per-vertex finger assignment ----------------
__global__ void prep_kernel(const float* __restrict__ pred,
                            const int* __restrict__ f0, int n0,
                            const int* __restrict__ f1, int n1,
                            const int* __restrict__ f2, int n2,
                            const int* __restrict__ f3, int n3,
                            const int* __restrict__ f4, int n4) {
    int t = threadIdx.x;
    for (int i = t; i < B3 * 5; i += 256) {
        int b = i / 5, f = i % 5;
        float p0 = pred[b * 10 + f];
        float p1 = pred[b * 10 + 5 + f];
        g_occ[i] = 1.f / (1.f + __expf(p1 - p0));
    }
    for (int i = t; i < NV; i += 256) g_assign[i] = -1;
    __syncthreads();
    if (t < n0) g_assign[f0[t]] = 0;
    __syncthreads();
    if (t < n1) g_assign[f1[t]] = 1;
    __syncthreads();
    if (t < n2) g_assign[f2[t]] = 2;
    __syncthreads();
    if (t < n3) g_assign[f3[t]] = 3;
    __syncthreads();
    if (t < n4) g_assign[f4[t]] = 4;
}

// ---------------- weight transpose + fp16 convert: dst[n][k] = (half)src[k][n] ----------------
__global__ void transconv_kernel(const float* __restrict__ src, __half* __restrict__ dst,
                                 int K, int N) {
    __shared__ float tile[32][33];
    int n0 = blockIdx.x * 32, k0 = blockIdx.y * 32;
    int x = threadIdx.x;
    for (int yy = threadIdx.y; yy < 32; yy += 8) {
        int k = k0 + yy, n = n0 + x;
        tile[yy][x] = (k < K && n < N) ? src[(size_t)k * N + n] : 0.f;
    }
    __syncthreads();
    for (int yy = threadIdx.y; yy < 32; yy += 8) {
        int n = n0 + yy, k = k0 + x;
        if (n < N && k < K) dst[(size_t)n * K + k] = __float2half_rn(tile[x][yy]);
    }
}

// ---------------- stage 1: weighted view fusion -> h0 = [wx | x[:B]] (fp16) ----------------
__global__ void h0_kernel(const float* __restrict__ x) {
    int v = blockIdx.x;
    int b = blockIdx.y;
    int c = threadIdx.x;
    int a = g_assign[v];
    float w0 = 1.f, w1 = 1.f, w2 = 1.f;
    if (a >= 0) {
        w0 = g_occ[(0 * NB + b) * 5 + a];
        w1 = g_occ[(1 * NB + b) * 5 + a];
        w2 = g_occ[(2 * NB + b) * 5 + a];
    }
    float m  = fmaxf(w0, fmaxf(w1, w2));
    float e0 = __expf(w0 - m), e1 = __expf(w1 - m), e2 = __expf(w2 - m);
    float inv = 1.f / (e0 + e1 + e2);
    size_t base = ((size_t)b * NV + v) * NC + c;
    const size_t gstride = (size_t)NB * NV * NC;
    float x0 = x[base];
    float x1 = x[base + gstride];
    float x2 = x[base + 2 * gstride];
    size_t ho = ((size_t)b * NV + v) * 512 + c;
    g_h0h[ho]       = __float2half_rn((e0 * x0 + e1 * x1 + e2 * x2) * inv);
    g_h0h[ho + 256] = __float2half_rn(x0);
}

// ---------------- fp16 mma.sync implicit-gather GEMM ----------------
// CTA 128x128, K-chunk 64 fp16 (128B rows, XOR-swizzled), cp.async double buffer,
// ldmatrix fragment loads. 8 warps: 2M x 4N, warp tile 64x32. 2 CTAs/SM.
#define OF_NBR 0
#define OF_A   4736
#define OF_B   (4736 + 32768)
#define SMEM_H (4736 + 65536)   // 70272 B

__device__ __forceinline__ uint32_t smem_u32(const void* p) {
    uint32_t a;
    asm("{ .reg .u64 t; cvta.to.shared.u64 t, %1; cvt.u32.u64 %0, t; }" : "=r"(a) : "l"(p));
    return a;
}
#define CPASYNC16(dst, src) \
    asm volatile("cp.async.cg.shared.global [%0], [%1], 16;" :: "r"(dst), "l"(src))
#define CPCOMMIT()  asm volatile("cp.async.commit_group;" ::: "memory")
#define CPWAIT0()   asm volatile("cp.async.wait_group 0;" ::: "memory")
#define LDSM4(r0, r1, r2, r3, addr) \
    asm volatile("ldmatrix.sync.aligned.m8n8.x4.shared.b16 {%0,%1,%2,%3}, [%4];" \
                 : "=r"(r0), "=r"(r1), "=r"(r2), "=r"(r3) : "r"(addr))
#define MMA16816(d, a, b) \
    asm volatile("mma.sync.aligned.m16n8k16.row.col.f32.f16.f16.f32 " \
                 "{%0,%1,%2,%3}, {%4,%5,%6,%7}, {%8,%9}, {%0,%1,%2,%3};" \
                 : "+f"(d[0]), "+f"(d[1]), "+f"(d[2]), "+f"(d[3]) \
                 : "r"(a[0]), "r"(a[1]), "r"(a[2]), "r"(a[3]), "r"(b[0]), "r"(b[1]))

template<int CIN, int KTOT, int COUT, int LOGCPW, bool OUTF32>
__global__ __launch_bounds__(256, 2)
void spiral_hmma(const __half* __restrict__ hin,
                 const __half* __restrict__ wt,    // [COUT][KTOT] fp16
                 const float* __restrict__ bias,
                 const int* __restrict__ idx,
                 void* __restrict__ houtv) {
    extern __shared__ char sm[];
    int* nb_s = (int*)(sm + OF_NBR);
    const uint32_t smA = smem_u32(sm + OF_A);
    const uint32_t smB = smem_u32(sm + OF_B);
    const int tid  = threadIdx.x;
    const int lane = tid & 31;
    const int wid  = tid >> 5;
    const int warpM = wid & 1;
    const int warpN = wid >> 1;
    const int n0 = blockIdx.x * 128;
    const int m0 = blockIdx.y * 128;

    if (tid < 128) {
        int grow = m0 + tid;
        int b = grow / NV;
        int v = grow - b * NV;
#pragma unroll
        for (int k = 0; k < NK; k++) nb_s[tid * NK + k] = b * NV + idx[v * NK + k];
    }
    __syncthreads();

    constexpr int CPW = CIN / 64;
    constexpr int NCH = KTOT / 64;

    // cp.async geometry: thread -> one row (m or n), 4 of 8 16B chunks
    const int lrow = tid >> 1;
    const int jh   = (tid & 1) * 4;
    const int lsw  = lrow & 7;
    const uint32_t adst0 = smA + (uint32_t)lrow * 128u;
    const uint32_t bdst0 = smB + (uint32_t)lrow * 128u;
    const __half* brow_src = wt + (size_t)(n0 + lrow) * KTOT;

#define LOAD_CHUNK(kc, buf)                                                        \
    {                                                                              \
        const int ks = (kc) >> LOGCPW;                                             \
        const int c0 = ((kc) & (CPW - 1)) * 64;                                    \
        const __half* asrc = hin + (size_t)nb_s[lrow * NK + ks] * CIN + c0;        \
        const uint32_t ad = adst0 + (uint32_t)(buf) * 16384u;                      \
        const uint32_t bd = bdst0 + (uint32_t)(buf) * 16384u;                      \
        const __half* bsrc = brow_src + (size_t)(kc) * 64;                         \
        _Pragma("unroll")                                                          \
        for (int jj = 0; jj < 4; jj++) {                                           \
            const int c = jh + jj;                                                 \
            CPASYNC16(ad + (uint32_t)((c ^ lsw) << 4), asrc + c * 8);              \
            CPASYNC16(bd + (uint32_t)((c ^ lsw) << 4), bsrc + c * 8);              \
        }                                                                          \
        CPCOMMIT();                                                                \
    }

    // ldmatrix geometry
    const int arow = warpM * 64 + (lane & 15);
    const int ahi  = (lane >> 4) & 1;
    const int asw  = arow & 7;
    const int brow = warpN * 32 + (lane & 7) + ((lane & 16) >> 1);
    const int bhi  = (lane >> 3) & 1;
    const int bsw  = brow & 7;
    const uint32_t aAddr0 = smA + (uint32_t)arow * 128u;
    const uint32_t bAddr0 = smB + (uint32_t)brow * 128u;

    // hoist bias (per-thread epilogue columns) before the mainloop
    const int c2 = (lane & 3) * 2;
    float bcol0[4], bcol1[4];
#pragma unroll
    for (int nt = 0; nt < 4; nt++) {
        const int col = n0 + warpN * 32 + nt * 8 + c2;
        bcol0[nt] = bias[col];
        bcol1[nt] = bias[col + 1];
    }

    float acc[4][4][4];
#pragma unroll
    for (int a = 0; a < 4; a++)
#pragma unroll
        for (int b = 0; b < 4; b++)
#pragma unroll
            for (int c = 0; c < 4; c++) acc[a][b][c] = 0.f;

    LOAD_CHUNK(0, 0);
    for (int kc = 0; kc < NCH; kc++) {
        const int buf = kc & 1;
        CPWAIT0();
        __syncthreads();
        if (kc + 1 < NCH) LOAD_CHUNK(kc + 1, buf ^ 1);
        const uint32_t aBuf = aAddr0 + (uint32_t)buf * 16384u;
        const uint32_t bBuf = bAddr0 + (uint32_t)buf * 16384u;
#pragma unroll
        for (int s = 0; s < 4; s++) {
            const uint32_t swa = (uint32_t)(((s * 2 + ahi) ^ asw) << 4);
            const uint32_t swb = (uint32_t)(((s * 2 + bhi) ^ bsw) << 4);
            uint32_t afr[4][4];
#pragma unroll
            for (int mt = 0; mt < 4; mt++)
                LDSM4(afr[mt][0], afr[mt][1], afr[mt][2], afr[mt][3],
                      aBuf + (uint32_t)(mt * 16 * 128) + swa);
            uint32_t bfr[4][2];
#pragma unroll
            for (int p = 0; p < 2; p++)
                LDSM4(bfr[p * 2][0], bfr[p * 2][1], bfr[p * 2 + 1][0], bfr[p * 2 + 1][1],
                      bBuf + (uint32_t)(p * 16 * 128) + swb);
#pragma unroll
            for (int mt = 0; mt < 4; mt++)
#pragma unroll
                for (int nt = 0; nt < 4; nt++)
                    MMA16816(acc[mt][nt], afr[mt], bfr[nt]);
        }
        __syncthreads();
    }

    // epilogue: bias + relu; fp16 out for next conv, fp32 for head input
    const int r4 = lane >> 2;
#pragma unroll
    for (int nt = 0; nt < 4; nt++) {
        const int col = n0 + warpN * 32 + nt * 8 + c2;
        const float b0v = bcol0[nt], b1v = bcol1[nt];
#pragma unroll
        for (int mt = 0; mt < 4; mt++) {
            const int row = m0 + warpM * 64 + mt * 16 + r4;
            float v0 = fmaxf(acc[mt][nt][0] + b0v, 0.f);
            float v1 = fmaxf(acc[mt][nt][1] + b1v, 0.f);
            float v2 = fmaxf(acc[mt][nt][2] + b0v, 0.f);
            float v3 = fmaxf(acc[mt][nt][3] + b1v, 0.f);
            if (OUTF32) {
                float* ho = (float*)houtv;
                *(float2*)(ho + (size_t)row * COUT + col) = make_float2(v0, v1);
                *(float2*)(ho + (size_t)(row + 8) * COUT + col) = make_float2(v2, v3);
            } else {
                __half2* ho = (__half2*)houtv;
                ho[((size_t)row * COUT + col) >> 1] = __floats2half2_rn(v0, v1);
                ho[((size_t)(row + 8) * COUT + col) >> 1] = __floats2half2_rn(v2, v3);
            }
        }
    }
#undef LOAD_CHUNK
}

// ---------------- head: Cout=3, one warp per (b,v) row ----------------
__global__ __launch_bounds__(256)
void head_kernel(const float* __restrict__ h3,
                 const float* __restrict__ wh,
                 const float* __restrict__ bh,
                 const int* __restrict__ idx,
                 float* __restrict__ out) {
    int warp = blockIdx.x * 8 + (threadIdx.x >> 5);
    int lane = threadIdx.x & 31;
    int b = warp / NV;
    int v = warp - b * NV;
    const float* hb = h3 + (size_t)b * NV * NC;
    float a0 = 0.f, a1 = 0.f, a2 = 0.f;
    for (int t = lane; t < NK * NC; t += 32) {
        int k = t >> 8;
        int c = t & 255;
        float a = hb[(size_t)idx[v * NK + k] * NC + c];
        const float* wr = wh + t * 3;
        a0 += a * wr[0];
        a1 += a * wr[1];
        a2 += a * wr[2];
    }
#pragma unroll
    for (int off = 16; off; off >>= 1) {
        a0 += __shfl_down_sync(0xffffffffu, a0, off);
        a1 += __shfl_down_sync(0xffffffffu, a1, off);
        a2 += __shfl_down_sync(0xffffffffu, a2, off);
    }
    if (lane == 0) {
        float* o = out + (size_t)warp * 3;
        o[0] = a0 + bh[0];
        o[1] = a1 + bh[1];
        o[2] = a2 + bh[2];
    }
}

// ---------------- launch ----------------
extern "C" void kernel_launch(void* const* d_in, const int* in_sizes, int n_in,
                              void* d_out, int out_size) {
    const float* x        = (const float*)d_in[0];
    const float* pred_occ = (const float*)d_in[1];
    const int*   indices  = (const int*)d_in[2];
    const int*   f0 = (const int*)d_in[3];
    const int*   f1 = (const int*)d_in[4];
    const int*   f2 = (const int*)d_in[5];
    const int*   f3 = (const int*)d_in[6];
    const int*   f4 = (const int*)d_in[7];
    const float* w0 = (const float*)d_in[8];
    const float* b0 = (const float*)d_in[9];
    const float* w1 = (const float*)d_in[10];
    const float* b1 = (const float*)d_in[11];
    const float* w2 = (const float*)d_in[12];
    const float* b2 = (const float*)d_in[13];
    const float* wh = (const float*)d_in[14];
    const float* bh = (const float*)d_in[15];
    float* out = (float*)d_out;

    __half *h0p, *h1p, *h2p, *wt0p, *wt1p, *wt2p;
    float *h3p;
    cudaGetSymbolAddress((void**)&h0p, g_h0h);
    cudaGetSymbolAddress((void**)&h1p, g_h1h);
    cudaGetSymbolAddress((void**)&h2p, g_h2h);
    cudaGetSymbolAddress((void**)&h3p, g_h3);
    cudaGetSymbolAddress((void**)&wt0p, g_wt0);
    cudaGetSymbolAddress((void**)&wt1p, g_wt1);
    cudaGetSymbolAddress((void**)&wt2p, g_wt2);

    cudaFuncSetAttribute(spiral_hmma<512, 4608, 512, 3, false>, cudaFuncAttributeMaxDynamicSharedMemorySize, SMEM_H);
    cudaFuncSetAttribute(spiral_hmma<512, 4608, 256, 3, false>, cudaFuncAttributeMaxDynamicSharedMemorySize, SMEM_H);
    cudaFuncSetAttribute(spiral_hmma<256, 2304, 256, 2, true>, cudaFuncAttributeMaxDynamicSharedMemorySize, SMEM_H);

    prep_kernel<<<1, 256>>>(pred_occ, f0, in_sizes[3], f1, in_sizes[4],
                            f2, in_sizes[5], f3, in_sizes[6], f4, in_sizes[7]);
    transconv_kernel<<<dim3(512 / 32, 4608 / 32), dim3(32, 8)>>>(w0, wt0p, 4608, 512);
    transconv_kernel<<<dim3(256 / 32, 4608 / 32), dim3(32, 8)>>>(w1, wt1p, 4608, 256);
    transconv_kernel<<<dim3(256 / 32, 2304 / 32), dim3(32, 8)>>>(w2, wt2p, 2304, 256);
    h0_kernel<<<dim3(NV, NB), 256>>>(x);

    spiral_hmma<512, 4608, 512, 3, false><<<dim3(4, 389), 256, SMEM_H>>>(h0p, wt0p, b0, indices, h1p);
    spiral_hmma<512, 4608, 256, 3, false><<<dim3(2, 389), 256, SMEM_H>>>(h1p, wt1p, b1, indices, h2p);
    spiral_hmma<256, 2304, 256, 2, true><<<dim3(2, 389), 256, SMEM_H>>>(h2p, wt2p, b2, indices, h3p);
    head_kernel<<<6224, 256>>>(h3p, wh, bh, indices, out);
}

// round 9
// speedup vs baseline: 1.3311x; 1.0391x over previous
#include <cuda_runtime.h>
#include <cuda_fp16.h>
#include <cstdint>

#define NV 778
#define NK 9
#define NC 256
#define NB 64
#define B3 192
#define MROWS (NB * NV)   // 49792 = 389 * 128 exactly

// ---------------- scratch (device globals; no runtime allocation) ----------------
__device__ __half g_h0h[(size_t)MROWS * 512];
__device__ __half g_h1h[(size_t)MROWS * 512];
__device__ __half g_h2h[(size_t)MROWS * 256];
__device__ float  g_h3 [(size_t)MROWS * 256];
__device__ __half g_wt0[512 * 4608];   // [N][K]
__device__ __half g_wt1[256 * 4608];
__device__ __half g_wt2[256 * 2304];
__device__ float  g_occ[B3 * 5];
__device__ int    g_assign[NV];

// ---------------- stage 0: occ + per-vertex finger assignment ----------------
__global__ void prep_kernel(const float* __restrict__ pred,
                            const int* __restrict__ f0, int n0,
                            const int* __restrict__ f1, int n1,
                            const int* __restrict__ f2, int n2,
                            const int* __restrict__ f3, int n3,
                            const int* __restrict__ f4, int n4) {
    int t = threadIdx.x;
    for (int i = t; i < B3 * 5; i += 256) {
        int b = i / 5, f = i % 5;
        float p0 = pred[b * 10 + f];
        float p1 = pred[b * 10 + 5 + f];
        g_occ[i] = 1.f / (1.f + __expf(p1 - p0));
    }
    for (int i = t; i < NV; i += 256) g_assign[i] = -1;
    __syncthreads();
    if (t < n0) g_assign[f0[t]] = 0;
    __syncthreads();
    if (t < n1) g_assign[f1[t]] = 1;
    __syncthreads();
    if (t < n2) g_assign[f2[t]] = 2;
    __syncthreads();
    if (t < n3) g_assign[f3[t]] = 3;
    __syncthreads();
    if (t < n4) g_assign[f4[t]] = 4;
}

// ---------------- weight transpose + fp16 convert: dst[n][k] = (half)src[k][n] ----------------
__global__ void transconv_kernel(const float* __restrict__ src, __half* __restrict__ dst,
                                 int K, int N) {
    __shared__ float tile[32][33];
    int n0 = blockIdx.x * 32, k0 = blockIdx.y * 32;
    int x = threadIdx.x;
    for (int yy = threadIdx.y; yy < 32; yy += 8) {
        int k = k0 + yy, n = n0 + x;
        tile[yy][x] = (k < K && n < N) ? src[(size_t)k * N + n] : 0.f;
    }
    __syncthreads();
    for (int yy = threadIdx.y; yy < 32; yy += 8) {
        int n = n0 + yy, k = k0 + x;
        if (n < N && k < K) dst[(size_t)n * K + k] = __float2half_rn(tile[x][yy]);
    }
}

// ---------------- stage 1: weighted view fusion -> h0 = [wx | x[:B]] (fp16) ----------------
__global__ void h0_kernel(const float* __restrict__ x) {
    int v = blockIdx.x;
    int b = blockIdx.y;
    int c = threadIdx.x;
    int a = g_assign[v];
    float w0 = 1.f, w1 = 1.f, w2 = 1.f;
    if (a >= 0) {
        w0 = g_occ[(0 * NB + b) * 5 + a];
        w1 = g_occ[(1 * NB + b) * 5 + a];
        w2 = g_occ[(2 * NB + b) * 5 + a];
    }
    float m  = fmaxf(w0, fmaxf(w1, w2));
    float e0 = __expf(w0 - m), e1 = __expf(w1 - m), e2 = __expf(w2 - m);
    float inv = 1.f / (e0 + e1 + e2);
    size_t base = ((size_t)b * NV + v) * NC + c;
    const size_t gstride = (size_t)NB * NV * NC;
    float x0 = x[base];
    float x1 = x[base + gstride];
    float x2 = x[base + 2 * gstride];
    size_t ho = ((size_t)b * NV + v) * 512 + c;
    g_h0h[ho]       = __float2half_rn((e0 * x0 + e1 * x1 + e2 * x2) * inv);
    g_h0h[ho + 256] = __float2half_rn(x0);
}

// ---------------- fp16 mma.sync implicit-gather GEMM ----------------
// CTA 128x128, K-chunk 64 fp16, 3-stage cp.async ring (wait_group 1),
// single barrier per chunk, ldmatrix fragments. 8 warps: 2M x 4N, warp 64x32.
#define OF_NBR  0
#define OF_TILE 4736
#define STG_SZ  32768u
#define SMEM_H  (OF_TILE + 3 * 32768)   // 103040 B -> 2 CTAs/SM

__device__ __forceinline__ uint32_t smem_u32(const void* p) {
    uint32_t a;
    asm("{ .reg .u64 t; cvta.to.shared.u64 t, %1; cvt.u32.u64 %0, t; }" : "=r"(a) : "l"(p));
    return a;
}
#define CPASYNC16(dst, src) \
    asm volatile("cp.async.cg.shared.global [%0], [%1], 16;" :: "r"(dst), "l"(src))
#define CPCOMMIT()  asm volatile("cp.async.commit_group;" ::: "memory")
#define CPWAIT(n)   asm volatile("cp.async.wait_group %0;" :: "n"(n) : "memory")
#define LDSM4(r0, r1, r2, r3, addr) \
    asm volatile("ldmatrix.sync.aligned.m8n8.x4.shared.b16 {%0,%1,%2,%3}, [%4];" \
                 : "=r"(r0), "=r"(r1), "=r"(r2), "=r"(r3) : "r"(addr))
#define MMA16816(d, a, b) \
    asm volatile("mma.sync.aligned.m16n8k16.row.col.f32.f16.f16.f32 " \
                 "{%0,%1,%2,%3}, {%4,%5,%6,%7}, {%8,%9}, {%0,%1,%2,%3};" \
                 : "+f"(d[0]), "+f"(d[1]), "+f"(d[2]), "+f"(d[3]) \
                 : "r"(a[0]), "r"(a[1]), "r"(a[2]), "r"(a[3]), "r"(b[0]), "r"(b[1]))

template<int CIN, int KTOT, int COUT, int LOGCPW, bool OUTF32>
__global__ __launch_bounds__(256)
void spiral_hmma(const __half* __restrict__ hin,
                 const __half* __restrict__ wt,    // [COUT][KTOT] fp16
                 const float* __restrict__ bias,
                 const int* __restrict__ idx,
                 void* __restrict__ houtv) {
    extern __shared__ char sm[];
    int* nb_s = (int*)(sm + OF_NBR);
    const uint32_t smT = smem_u32(sm + OF_TILE);
    const int tid  = threadIdx.x;
    const int lane = tid & 31;
    const int wid  = tid >> 5;
    const int warpM = wid & 1;
    const int warpN = wid >> 1;
    const int n0 = blockIdx.x * 128;
    const int m0 = blockIdx.y * 128;

    if (tid < 128) {
        int grow = m0 + tid;
        int b = grow / NV;
        int v = grow - b * NV;
#pragma unroll
        for (int k = 0; k < NK; k++) nb_s[tid * NK + k] = b * NV + idx[v * NK + k];
    }
    __syncthreads();

    constexpr int CPW = CIN / 64;
    constexpr int NCH = KTOT / 64;

    // cp.async geometry: thread -> one row (m or n), 4 of 8 16B chunks
    const int lrow = tid >> 1;
    const int jh   = (tid & 1) * 4;
    const int lsw  = lrow & 7;
    const uint32_t adst0 = smT + (uint32_t)lrow * 128u;
    const uint32_t bdst0 = smT + 16384u + (uint32_t)lrow * 128u;
    const __half* brow_src = wt + (size_t)(n0 + lrow) * KTOT;

#define LOAD_CHUNK(kc, stg)                                                        \
    {                                                                              \
        const int ks = (kc) >> LOGCPW;                                             \
        const int c0 = ((kc) & (CPW - 1)) * 64;                                    \
        const __half* asrc = hin + (size_t)nb_s[lrow * NK + ks] * CIN + c0;        \
        const uint32_t ad = adst0 + (uint32_t)(stg) * STG_SZ;                      \
        const uint32_t bd = bdst0 + (uint32_t)(stg) * STG_SZ;                      \
        const __half* bsrc = brow_src + (size_t)(kc) * 64;                         \
        _Pragma("unroll")                                                          \
        for (int jj = 0; jj < 4; jj++) {                                           \
            const int c = jh + jj;                                                 \
            CPASYNC16(ad + (uint32_t)((c ^ lsw) << 4), asrc + c * 8);              \
            CPASYNC16(bd + (uint32_t)((c ^ lsw) << 4), bsrc + c * 8);              \
        }                                                                          \
        CPCOMMIT();                                                                \
    }

    // ldmatrix geometry
    const int arow = warpM * 64 + (lane & 15);
    const int ahi  = (lane >> 4) & 1;
    const int asw  = arow & 7;
    const int brow = warpN * 32 + (lane & 7) + ((lane & 16) >> 1);
    const int bhi  = (lane >> 3) & 1;
    const int bsw  = brow & 7;
    const uint32_t aAddr0 = smT + (uint32_t)arow * 128u;
    const uint32_t bAddr0 = smT + 16384u + (uint32_t)brow * 128u;

    // hoist bias (per-thread epilogue columns) before the mainloop
    const int c2 = (lane & 3) * 2;
    float bcol0[4], bcol1[4];
#pragma unroll
    for (int nt = 0; nt < 4; nt++) {
        const int col = n0 + warpN * 32 + nt * 8 + c2;
        bcol0[nt] = bias[col];
        bcol1[nt] = bias[col + 1];
    }

    float acc[4][4][4];
#pragma unroll
    for (int a = 0; a < 4; a++)
#pragma unroll
        for (int b = 0; b < 4; b++)
#pragma unroll
            for (int c = 0; c < 4; c++) acc[a][b][c] = 0.f;

    LOAD_CHUNK(0, 0);
    LOAD_CHUNK(1, 1);
    int cur = 0;   // stage holding chunk kc
    for (int kc = 0; kc < NCH; kc++) {
        if (kc + 1 < NCH) { CPWAIT(1); } else { CPWAIT(0); }
        __syncthreads();   // single barrier: orders cp.async visibility AND ring-slot reuse
        if (kc + 2 < NCH) {
            int ns = cur + 2; if (ns >= 3) ns -= 3;
            LOAD_CHUNK(kc + 2, ns);
        }
        const uint32_t aBuf = aAddr0 + (uint32_t)cur * STG_SZ;
        const uint32_t bBuf = bAddr0 + (uint32_t)cur * STG_SZ;
#pragma unroll
        for (int s = 0; s < 4; s++) {
            const uint32_t swa = (uint32_t)(((s * 2 + ahi) ^ asw) << 4);
            const uint32_t swb = (uint32_t)(((s * 2 + bhi) ^ bsw) << 4);
            uint32_t afr[4][4];
#pragma unroll
            for (int mt = 0; mt < 4; mt++)
                LDSM4(afr[mt][0], afr[mt][1], afr[mt][2], afr[mt][3],
                      aBuf + (uint32_t)(mt * 16 * 128) + swa);
            uint32_t bfr[4][2];
#pragma unroll
            for (int p = 0; p < 2; p++)
                LDSM4(bfr[p * 2][0], bfr[p * 2][1], bfr[p * 2 + 1][0], bfr[p * 2 + 1][1],
                      bBuf + (uint32_t)(p * 16 * 128) + swb);
#pragma unroll
            for (int mt = 0; mt < 4; mt++)
#pragma unroll
                for (int nt = 0; nt < 4; nt++)
                    MMA16816(acc[mt][nt], afr[mt], bfr[nt]);
        }
        cur++; if (cur == 3) cur = 0;
    }

    // epilogue: bias + relu; fp16 out for next conv, fp32 for head input
    const int r4 = lane >> 2;
#pragma unroll
    for (int nt = 0; nt < 4; nt++) {
        const int col = n0 + warpN * 32 + nt * 8 + c2;
        const float b0v = bcol0[nt], b1v = bcol1[nt];
#pragma unroll
        for (int mt = 0; mt < 4; mt++) {
            const int row = m0 + warpM * 64 + mt * 16 + r4;
            float v0 = fmaxf(acc[mt][nt][0] + b0v, 0.f);
            float v1 = fmaxf(acc[mt][nt][1] + b1v, 0.f);
            float v2 = fmaxf(acc[mt][nt][2] + b0v, 0.f);
            float v3 = fmaxf(acc[mt][nt][3] + b1v, 0.f);
            if (OUTF32) {
                float* ho = (float*)houtv;
                *(float2*)(ho + (size_t)row * COUT + col) = make_float2(v0, v1);
                *(float2*)(ho + (size_t)(row + 8) * COUT + col) = make_float2(v2, v3);
            } else {
                __half2* ho = (__half2*)houtv;
                ho[((size_t)row * COUT + col) >> 1] = __floats2half2_rn(v0, v1);
                ho[((size_t)(row + 8) * COUT + col) >> 1] = __floats2half2_rn(v2, v3);
            }
        }
    }
#undef LOAD_CHUNK
}

// ---------------- head: Cout=3, one warp per (b,v) row ----------------
__global__ __launch_bounds__(256)
void head_kernel(const float* __restrict__ h3,
                 const float* __restrict__ wh,
                 const float* __restrict__ bh,
                 const int* __restrict__ idx,
                 float* __restrict__ out) {
    int warp = blockIdx.x * 8 + (threadIdx.x >> 5);
    int lane = threadIdx.x & 31;
    int b = warp / NV;
    int v = warp - b * NV;
    const float* hb = h3 + (size_t)b * NV * NC;
    float a0 = 0.f, a1 = 0.f, a2 = 0.f;
    for (int t = lane; t < NK * NC; t += 32) {
        int k = t >> 8;
        int c = t & 255;
        float a = hb[(size_t)idx[v * NK + k] * NC + c];
        const float* wr = wh + t * 3;
        a0 += a * wr[0];
        a1 += a * wr[1];
        a2 += a * wr[2];
    }
#pragma unroll
    for (int off = 16; off; off >>= 1) {
        a0 += __shfl_down_sync(0xffffffffu, a0, off);
        a1 += __shfl_down_sync(0xffffffffu, a1, off);
        a2 += __shfl_down_sync(0xffffffffu, a2, off);
    }
    if (lane == 0) {
        float* o = out + (size_t)warp * 3;
        o[0] = a0 + bh[0];
        o[1] = a1 + bh[1];
        o[2] = a2 + bh[2];
    }
}

// ---------------- launch ----------------
extern "C" void kernel_launch(void* const* d_in, const int* in_sizes, int n_in,
                              void* d_out, int out_size) {
    const float* x        = (const float*)d_in[0];
    const float* pred_occ = (const float*)d_in[1];
    const int*   indices  = (const int*)d_in[2];
    const int*   f0 = (const int*)d_in[3];
    const int*   f1 = (const int*)d_in[4];
    const int*   f2 = (const int*)d_in[5];
    const int*   f3 = (const int*)d_in[6];
    const int*   f4 = (const int*)d_in[7];
    const float* w0 = (const float*)d_in[8];
    const float* b0 = (const float*)d_in[9];
    const float* w1 = (const float*)d_in[10];
    const float* b1 = (const float*)d_in[11];
    const float* w2 = (const float*)d_in[12];
    const float* b2 = (const float*)d_in[13];
    const float* wh = (const float*)d_in[14];
    const float* bh = (const float*)d_in[15];
    float* out = (float*)d_out;

    __half *h0p, *h1p, *h2p, *wt0p, *wt1p, *wt2p;
    float *h3p;
    cudaGetSymbolAddress((void**)&h0p, g_h0h);
    cudaGetSymbolAddress((void**)&h1p, g_h1h);
    cudaGetSymbolAddress((void**)&h2p, g_h2h);
    cudaGetSymbolAddress((void**)&h3p, g_h3);
    cudaGetSymbolAddress((void**)&wt0p, g_wt0);
    cudaGetSymbolAddress((void**)&wt1p, g_wt1);
    cudaGetSymbolAddress((void**)&wt2p, g_wt2);

    cudaFuncSetAttribute(spiral_hmma<512, 4608, 512, 3, false>, cudaFuncAttributeMaxDynamicSharedMemorySize, SMEM_H);
    cudaFuncSetAttribute(spiral_hmma<512, 4608, 256, 3, false>, cudaFuncAttributeMaxDynamicSharedMemorySize, SMEM_H);
    cudaFuncSetAttribute(spiral_hmma<256, 2304, 256, 2, true>, cudaFuncAttributeMaxDynamicSharedMemorySize, SMEM_H);

    prep_kernel<<<1, 256>>>(pred_occ, f0, in_sizes[3], f1, in_sizes[4],
                            f2, in_sizes[5], f3, in_sizes[6], f4, in_sizes[7]);
    transconv_kernel<<<dim3(512 / 32, 4608 / 32), dim3(32, 8)>>>(w0, wt0p, 4608, 512);
    transconv_kernel<<<dim3(256 / 32, 4608 / 32), dim3(32, 8)>>>(w1, wt1p, 4608, 256);
    transconv_kernel<<<dim3(256 / 32, 2304 / 32), dim3(32, 8)>>>(w2, wt2p, 2304, 256);
    h0_kernel<<<dim3(NV, NB), 256>>>(x);

    spiral_hmma<512, 4608, 512, 3, false><<<dim3(4, 389), 256, SMEM_H>>>(h0p, wt0p, b0, indices, h1p);
    spiral_hmma<512, 4608, 256, 3, false><<<dim3(2, 389), 256, SMEM_H>>>(h1p, wt1p, b1, indices, h2p);
    spiral_hmma<256, 2304, 256, 2, true><<<dim3(2, 389), 256, SMEM_H>>>(h2p, wt2p, b2, indices, h3p);
    head_kernel<<<6224, 256>>>(h3p, wh, bh, indices, out);
}